// round 3
// baseline (speedup 1.0000x reference)
#include <cuda_runtime.h>
#include <cuda_bf16.h>

// Problem constants
#define KSZ   15
#define PAD   10
#define RSZ   128
#define L1    134            // R + 2*PAD - K + 1
#define MQ    17956          // L1*L1 queries
#define MPAD  18048          // 141 * 128
#define NMEM  16384
#define KDIM  225
#define KP2   120            // padded K/2  (K padded to 240)
#define CK2   24             // k2 per B chunk
#define NCH   (KP2/CK2)      // 5 chunks
#define MT    128            // queries per block
#define GEMM_BLOCKS (MPAD/MT)            // 141
#define SMEM_BYTES  ((KP2*MT + CK2*MT) * (int)sizeof(float2))  // 147456

// -------- device scratch (static globals: no runtime allocation) ----------
__device__ float2 g_Xt2[KP2 * MPAD];    // [k2][q]  even/odd k packed
__device__ float2 g_memT2[KP2 * NMEM];  // [k2][j]  even/odd k packed
__device__ float  g_norms[NMEM];
__device__ int    g_idx[MPAD];
__device__ float  g_raw[64 * 64];

// -------- packed fp32x2 FMA (Blackwell FFMA2, PTX-only) -------------------
__device__ __forceinline__ unsigned long long fma2(unsigned long long a,
                                                   unsigned long long b,
                                                   unsigned long long c) {
    unsigned long long d;
    asm("fma.rn.f32x2 %0, %1, %2, %3;" : "=l"(d) : "l"(a), "l"(b), "l"(c));
    return d;
}

// ---------------------------------------------------------------------------
// Prep 1: build packed query planes Xt2[k2][q] from the 64x64 image.
// x[q][k] = pad[r+i][c+j], q=r*134+c, k=i*15+j,
// pad(y,x) = image[(y-10)>>1][(x-10)>>1] inside [10,138), else 0.
// ---------------------------------------------------------------------------
__device__ __forceinline__ float sample_plane(const float* __restrict__ image,
                                              int r, int c, int k) {
    if (k >= KDIM) return 0.f;
    int i = k / KSZ, j = k - i * KSZ;
    int y = r + i - PAD, x = c + j - PAD;   // coords in the 128x128 upsampled img
    if ((unsigned)y < 128u && (unsigned)x < 128u)
        return image[(y >> 1) * 64 + (x >> 1)];
    return 0.f;
}

__global__ void prep_xt(const float* __restrict__ image) {
    int e = blockIdx.x * 256 + threadIdx.x;
    if (e >= KP2 * MPAD) return;
    int k2 = e / MPAD;
    int q  = e - k2 * MPAD;
    float2 v = make_float2(0.f, 0.f);
    if (q < MQ) {
        int r = q / L1, c = q - r * L1;
        v.x = sample_plane(image, r, c, 2 * k2);
        v.y = sample_plane(image, r, c, 2 * k2 + 1);
    }
    g_Xt2[e] = v;
}

// ---------------------------------------------------------------------------
// Prep 2: transpose+pack mem -> memT2[k2][j] (zeros beyond k=224)
// ---------------------------------------------------------------------------
__global__ void prep_memt(const float* __restrict__ mem) {
    int e = blockIdx.x * 256 + threadIdx.x;
    if (e >= KP2 * NMEM) return;
    int k2 = e >> 14;            // / 16384
    int j  = e & (NMEM - 1);
    int k0 = 2 * k2;
    float2 v;
    v.x = (k0     < KDIM) ? mem[j * KDIM + k0]     : 0.f;
    v.y = (k0 + 1 < KDIM) ? mem[j * KDIM + k0 + 1] : 0.f;
    g_memT2[e] = v;
}

// Prep 3: squared norms, one warp per mem row
__global__ void prep_norms(const float* __restrict__ mem) {
    int gw   = (blockIdx.x * blockDim.x + threadIdx.x) >> 5;
    int lane = threadIdx.x & 31;
    if (gw >= NMEM) return;
    const float* row = mem + gw * KDIM;
    float s = 0.f;
    for (int k = lane; k < KDIM; k += 32) { float v = row[k]; s += v * v; }
    #pragma unroll
    for (int o = 16; o; o >>= 1) s += __shfl_down_sync(0xffffffffu, s, o);
    if (lane == 0) g_norms[gw] = s;
}

// ---------------------------------------------------------------------------
// Fused GEMM + argmin.
// Block: 128 queries, loops over all 16384 candidates in tiles of 128.
// Threads: 256 = 32(tx, N) x 8(ty = warp, M). Thread tile: 16(m) x 4(n).
// A tile fully resident in smem; B streamed in 24-k2 chunks.
// A smem loads: warp-uniform broadcast. B smem loads: dense 512B, conflict-free.
// ---------------------------------------------------------------------------
__global__ void __launch_bounds__(256, 1) gemm_argmin() {
    extern __shared__ unsigned char smraw[];
    float2* As = (float2*)smraw;        // [KP2][128]
    float2* Bs = As + KP2 * MT;         // [CK2][128]

    const int tid = threadIdx.x;
    const int tx  = tid & 31;
    const int ty  = tid >> 5;
    const int qbase = blockIdx.x * MT;

    // Load the full A tile (128 queries x 120 packed-k) into smem.
    for (int i = tid; i < KP2 * MT; i += 256) {
        int k2 = i >> 7, m = i & 127;
        As[i] = g_Xt2[k2 * MPAD + qbase + m];
    }

    float minv[16];
    int   mini[16];
    #pragma unroll
    for (int r = 0; r < 16; r++) { minv[r] = 3.4e38f; mini[r] = 0; }

    for (int jt = 0; jt < NMEM; jt += 128) {
        unsigned long long acc[16][4];
        #pragma unroll
        for (int r = 0; r < 16; r++)
            #pragma unroll
            for (int c = 0; c < 4; c++) acc[r][c] = 0ull;

        for (int ch = 0; ch < NCH; ch++) {
            __syncthreads();   // previous chunk fully consumed
            for (int i = tid; i < CK2 * 128; i += 256) {
                Bs[i] = g_memT2[(ch * CK2 + (i >> 7)) * NMEM + jt + (i & 127)];
            }
            __syncthreads();

            #pragma unroll 2
            for (int kk = 0; kk < CK2; kk++) {
                const ulonglong2* Ar =
                    (const ulonglong2*)(As + (ch * CK2 + kk) * MT + ty * 16);
                const ulonglong2* Br =
                    (const ulonglong2*)(Bs + kk * MT);

                unsigned long long a[16], b[4];
                #pragma unroll
                for (int i = 0; i < 8; i++) {        // warp-uniform broadcast
                    ulonglong2 v = Ar[i];
                    a[2 * i] = v.x; a[2 * i + 1] = v.y;
                }
                {                                     // dense, conflict-free
                    ulonglong2 v0 = Br[tx];           // n = 2tx, 2tx+1
                    ulonglong2 v1 = Br[32 + tx];      // n = 64+2tx, 65+2tx
                    b[0] = v0.x; b[1] = v0.y; b[2] = v1.x; b[3] = v1.y;
                }
                #pragma unroll
                for (int r = 0; r < 16; r++)
                    #pragma unroll
                    for (int c = 0; c < 4; c++)
                        acc[r][c] = fma2(a[r], b[c], acc[r][c]);
            }
        }

        // distance + running argmin (j strictly ascending per thread -> '<'
        // keeps the first/lowest index, matching jnp.argmin)
        #pragma unroll
        for (int c = 0; c < 4; c++) {
            int j = jt + (c >> 1) * 64 + tx * 2 + (c & 1);
            float nrm = g_norms[j];
            #pragma unroll
            for (int r = 0; r < 16; r++) {
                float lo = __uint_as_float((unsigned)(acc[r][c]));
                float hi = __uint_as_float((unsigned)(acc[r][c] >> 32));
                float d  = nrm - 2.0f * (lo + hi);
                if (d < minv[r]) { minv[r] = d; mini[r] = j; }
            }
        }
    }

    // cross-thread (tx) argmin reduction per row, lexicographic tie-break
    __syncthreads();
    float* sv = (float*)smraw;                 // [128][32]
    int*   si = (int*)(sv + 128 * 32);         // [128][32]
    #pragma unroll
    for (int r = 0; r < 16; r++) {
        int row = ty * 16 + r;
        sv[row * 32 + tx] = minv[r];
        si[row * 32 + tx] = mini[r];
    }
    __syncthreads();
    if (tid < 128) {
        float best = 3.4e38f; int bi = 0x7fffffff;
        for (int t = 0; t < 32; t++) {
            float v = sv[tid * 32 + t];
            int  id = si[tid * 32 + t];
            if (v < best || (v == best && id < bi)) { best = v; bi = id; }
        }
        g_idx[qbase + tid] = bi;
    }
}

// ---------------------------------------------------------------------------
// Reconstruction: only the 64x64 subsampled grid of the folded accumulator
// is ever observed: out_raw[a][b] = acc[2a+10][2b+10]
//                 = sum_{i,j} mem[ idx[(y-i)*134 + (x-j)] ][ i*15+j ]
// ---------------------------------------------------------------------------
__global__ void recon(const float* __restrict__ mem) {
    int t = blockIdx.x * 256 + threadIdx.x;      // 0..4095
    if (t >= 4096) return;
    int a = t >> 6, b = t & 63;
    int y = 2 * a + PAD, x = 2 * b + PAD;
    float s = 0.f;
    #pragma unroll
    for (int i = 0; i < KSZ; i++) {
        int ry = y - i;
        if ((unsigned)ry >= (unsigned)L1) continue;
        int rowbase = ry * L1;
        #pragma unroll
        for (int j = 0; j < KSZ; j++) {
            int rx = x - j;
            if ((unsigned)rx >= (unsigned)L1) continue;
            s += mem[g_idx[rowbase + rx] * KDIM + i * KSZ + j];
        }
    }
    g_raw[t] = s;
}

// max-normalize (single block)
__global__ void normalize_out(float* __restrict__ out) {
    __shared__ float sm[256];
    int tid = threadIdx.x;
    float mx = -3.4e38f;
    for (int i = tid; i < 4096; i += 256) mx = fmaxf(mx, g_raw[i]);
    sm[tid] = mx;
    __syncthreads();
    for (int o = 128; o; o >>= 1) {
        if (tid < o) sm[tid] = fmaxf(sm[tid], sm[tid + o]);
        __syncthreads();
    }
    float m = sm[0];
    for (int i = tid; i < 4096; i += 256) out[i] = g_raw[i] / m;
}

// ---------------------------------------------------------------------------
extern "C" void kernel_launch(void* const* d_in, const int* in_sizes, int n_in,
                              void* d_out, int out_size) {
    const float* image = (const float*)d_in[0];   // 64*64
    const float* mem   = (const float*)d_in[1];   // 16384*225
    float* out = (float*)d_out;                   // 64*64

    cudaFuncSetAttribute(gemm_argmin,
                         cudaFuncAttributeMaxDynamicSharedMemorySize,
                         SMEM_BYTES);

    {
        int n = KP2 * MPAD;
        prep_xt<<<(n + 255) / 256, 256>>>(image);
    }
    {
        int n = KP2 * NMEM;
        prep_memt<<<(n + 255) / 256, 256>>>(mem);
    }
    prep_norms<<<(NMEM * 32) / 256, 256>>>(mem);

    gemm_argmin<<<GEMM_BLOCKS, 256, SMEM_BYTES>>>();

    recon<<<16, 256>>>(mem);
    normalize_out<<<1, 256>>>(out);
}